// round 17
// baseline (speedup 1.0000x reference)
#include <cuda_runtime.h>
#include <cuda_bf16.h>
#include <math.h>

#define BB 64
#define SS 256
#define HH 80
#define TT 600
#define CC 512
#define K2 576
#define GRID 128
#define NTHR 1024

__device__ __nv_bfloat16 g_xh[2][K2][128];
__device__ __nv_bfloat16 g_xl[2][K2][128];
__device__ __nv_bfloat16 g_wph[K2][4096];
__device__ __nv_bfloat16 g_wpl[K2][4096];
__device__ __nv_bfloat16 g_w1p[2][256][1024];
__device__ __nv_bfloat16 g_w2p[2][256][352];
__device__ __nv_bfloat16 g_t1p[2][256][128];
__device__ float g_qf[CC][BB];
__device__ float g_dk[BB][176];
__device__ float g_sp[256][20];
__device__ float g_lf[BB][2][128][8];
__device__ float g_pri[BB][2][128];
__device__ float g_energy[BB][SS];
__device__ float g_alpha[BB][SS];
__device__ unsigned g_fa[GRID * 8];
__device__ unsigned g_fb[GRID * 8];
__device__ unsigned g_df[GRID * 8];
__device__ unsigned g_fe[GRID * 8];
__device__ unsigned g_ff[GRID * 8];

__device__ __forceinline__ float sig_fast(float x) {
    return __fdividef(1.f, 1.f + __expf(-x));
}
__device__ __forceinline__ float tanh_fast(float x) {
    float e = __expf(2.f * x);
    return 1.f - __fdividef(2.f, e + 1.f);
}
__device__ __forceinline__ float tanh_mufu(float x) {
    float r;
    asm("tanh.approx.f32 %0,%1;" : "=f"(r) : "f"(x));
    return r;
}
__device__ __forceinline__ void st_rel(unsigned* p, unsigned v) {
    asm volatile("st.release.gpu.global.u32 [%0],%1;" :: "l"(p), "r"(v) : "memory");
}
__device__ __forceinline__ unsigned ld_acq(const unsigned* p) {
    unsigned v;
    asm volatile("ld.acquire.gpu.global.u32 %0,[%1];" : "=r"(v) : "l"(p) : "memory");
    return v;
}
__device__ __forceinline__ void cpg(unsigned d, const void* s) {
    asm volatile("cp.async.cg.shared.global [%0],[%1],16;" :: "r"(d), "l"(s));
}
__device__ __forceinline__ void cpw(unsigned d, const void* s) {
    asm volatile("cp.async.ca.shared.global [%0],[%1],16;" :: "r"(d), "l"(s));
}
#define CPC asm volatile("cp.async.commit_group;" ::: "memory")
#define CPW1 asm volatile("cp.async.wait_group 1;" ::: "memory")
#define CPW0 asm volatile("cp.async.wait_group 0;" ::: "memory")

__device__ __forceinline__ void mma_bf16(float& c0, float& c1, float& c2, float& c3,
                                         unsigned a0, unsigned a1, unsigned a2, unsigned a3,
                                         unsigned b0, unsigned b1) {
    asm volatile("mma.sync.aligned.m16n8k16.row.col.f32.bf16.bf16.f32 "
                 "{%0,%1,%2,%3},{%4,%5,%6,%7},{%8,%9},{%0,%1,%2,%3};"
                 : "+f"(c0), "+f"(c1), "+f"(c2), "+f"(c3)
                 : "r"(a0), "r"(a1), "r"(a2), "r"(a3), "r"(b0), "r"(b1));
}
__device__ __forceinline__ void fma2(unsigned long long& d, unsigned long long a,
                                     unsigned long long b) {
    asm("fma.rn.f32x2 %0, %1, %2, %0;" : "+l"(d) : "l"(a), "l"(b));
}

__global__ void k_init(const float* wi, const float* wh, const float* w1,
                       const float* w2, const float* lp, const float* dw,
                       const float* db, const float* aw) {
    int idx = blockIdx.x * blockDim.x + threadIdx.x;
    int stride = gridDim.x * blockDim.x;
    for (int i = idx; i < K2 * 4096; i += stride) {
        int k2 = i >> 12, np = i & 4095, n = np >> 1, p = np & 1, k = k2 * 2 + p;
        int ch = n >> 2, g = n & 3;
        float v = 0.f;
        if (k < 592) {
            if (g == 0) v = wi[ch * 592 + k];
            else if (g == 1) v = wi[(512 + ch) * 592 + k];
            else if (g == 2) v = wi[(1024 + ch) * 592 + k];
        } else if (k < 1104) {
            int kk = k - 592;
            if (g == 0) v = wh[ch * 512 + kk];
            else if (g == 1) v = wh[(512 + ch) * 512 + kk];
            else if (g == 3) v = wh[(1024 + ch) * 512 + kk];
        }
        __nv_bfloat16 h = __float2bfloat16(v);
        g_wph[k2][np] = h;
        g_wpl[k2][np] = __float2bfloat16(v - __bfloat162float(h));
    }
    for (int i = idx; i < 256 * 1024; i += stride) {
        int k2 = i >> 10, np = i & 1023, c = np >> 1, p = np & 1, k = k2 * 2 + p;
        float v = w1[c * 512 + k];
        __nv_bfloat16 h = __float2bfloat16(v);
        g_w1p[0][k2][np] = h;
        g_w1p[1][k2][np] = __float2bfloat16(v - __bfloat162float(h));
    }
    for (int i = idx; i < 256 * 352; i += stride) {
        int k2 = i / 352, np = i % 352, c = np >> 1, p = np & 1, k = k2 * 2 + p;
        float v = (c < 168) ? w2[c * 512 + k] : 0.f;
        __nv_bfloat16 h = __float2bfloat16(v);
        g_w2p[0][k2][np] = h;
        g_w2p[1][k2][np] = __float2bfloat16(v - __bfloat162float(h));
    }
    for (int i = idx; i < 2 * K2 * 128; i += stride) {
        ((__nv_bfloat16*)g_xh)[i] = __float2bfloat16(0.f);
        ((__nv_bfloat16*)g_xl)[i] = __float2bfloat16(0.f);
    }
    for (int i = idx; i < CC * BB; i += stride) ((float*)g_qf)[i] = 0.f;
    for (int i = idx; i < 256 * 20; i += stride) {
        int c = i / 20, j = i % 20;
        float v = 0.f;
        if (j < 8) v = lp[c * 8 + j];
        else if (j < 16) v = dw[c * 8 + (j - 8)];
        else if (j == 16) v = db[c];
        else if (j == 17) v = aw[c];
        g_sp[c][j] = v;
    }
    for (int i = idx; i < GRID * 8; i += stride) {
        g_fa[i] = 0u; g_fb[i] = 0u; g_df[i] = 0u; g_fe[i] = 0u; g_ff[i] = 0u;
    }
}

__device__ __forceinline__ void st_pair(int buf, int k, int b, float v) {
    __nv_bfloat16 h = __float2bfloat16(v);
    g_xh[buf][k >> 1][b * 2 + (k & 1)] = h;
    g_xl[buf][k >> 1][b * 2 + (k & 1)] = __float2bfloat16(v - __bfloat162float(h));
}

// bf16 hi/lo MMA GEMM, tile 32b x 16c, K=512 (8 chunks of 32 k2).
__device__ __forceinline__ void mma16(const __nv_bfloat16* ah, const __nv_bfloat16* al,
                                      const __nv_bfloat16* wh, const __nv_bfloat16* wl,
                                      int wstride, int c0, int b0,
                                      const float* bias, int mode,
                                      float* sm, int tid) {
    char* smc = (char*)sm;
    const int BUF = 16384;
    unsigned sbase = (unsigned)__cvta_generic_to_shared(smc);
    int lane = tid & 31;
    int wid = tid >> 5;
    int kz = wid & 3, tile = wid >> 2;
    int mi = tile & 1, ni = tile >> 1;
    int gid = lane >> 2, tig = lane & 3;
    int aoff = (kz * 8 + tig) * 160 + (mi * 16 + gid) * 4;
    int boff = 10240 + (kz * 8 + tig) * 96 + (ni * 8 + gid) * 4;
    float c0r = 0.f, c1r = 0.f, c2r = 0.f, c3r = 0.f;

    #pragma unroll
    for (int pg = 0; pg < 2; pg++) {
        int kc2 = pg * 32;
        if (tid < 512) {
            int grp = tid >> 8, row = (tid >> 3) & 31, seg = tid & 7;
            unsigned dst = sbase + (unsigned)(pg * BUF + grp * 5120 + row * 160 + seg * 16);
            const char* src = (const char*)(grp ? al : ah)
                            + (size_t)(kc2 + row) * 256 + b0 * 4 + seg * 16;
            cpg(dst, src);
        } else if (tid < 768) {
            int u = tid - 512, grp = u >> 7, row = (u >> 2) & 31, seg = u & 3;
            unsigned dst = sbase + (unsigned)(pg * BUF + 10240 + grp * 3072 + row * 96 + seg * 16);
            const char* src = (const char*)(grp ? wl : wh)
                            + (size_t)(kc2 + row) * wstride * 2 + c0 * 4 + seg * 16;
            cpw(dst, src);
        }
        CPC;
    }
    for (int ch = 0; ch < 8; ch++) {
        if (ch < 7) CPW1; else CPW0;
        __syncthreads();
        if (ch + 2 < 8) {
            int kc2 = (ch + 2) * 32, st = (ch + 2) % 3;
            if (tid < 512) {
                int grp = tid >> 8, row = (tid >> 3) & 31, seg = tid & 7;
                unsigned dst = sbase + (unsigned)(st * BUF + grp * 5120 + row * 160 + seg * 16);
                const char* src = (const char*)(grp ? al : ah)
                                + (size_t)(kc2 + row) * 256 + b0 * 4 + seg * 16;
                cpg(dst, src);
            } else if (tid < 768) {
                int u = tid - 512, grp = u >> 7, row = (u >> 2) & 31, seg = u & 3;
                unsigned dst = sbase + (unsigned)(st * BUF + 10240 + grp * 3072 + row * 96 + seg * 16);
                const char* src = (const char*)(grp ? wl : wh)
                                + (size_t)(kc2 + row) * wstride * 2 + c0 * 4 + seg * 16;
                cpw(dst, src);
            }
            CPC;
        }
        if (wid < 16) {
            const char* tb = smc + (ch % 3) * BUF;
            unsigned ah0 = *(const unsigned*)(tb + aoff);
            unsigned ah1 = *(const unsigned*)(tb + aoff + 32);
            unsigned ah2 = *(const unsigned*)(tb + aoff + 640);
            unsigned ah3 = *(const unsigned*)(tb + aoff + 672);
            unsigned al0 = *(const unsigned*)(tb + 5120 + aoff);
            unsigned al1 = *(const unsigned*)(tb + 5120 + aoff + 32);
            unsigned al2 = *(const unsigned*)(tb + 5120 + aoff + 640);
            unsigned al3 = *(const unsigned*)(tb + 5120 + aoff + 672);
            unsigned bh0 = *(const unsigned*)(tb + boff);
            unsigned bh1 = *(const unsigned*)(tb + boff + 384);
            unsigned bl0 = *(const unsigned*)(tb + 3072 + boff);
            unsigned bl1 = *(const unsigned*)(tb + 3072 + boff + 384);
            mma_bf16(c0r, c1r, c2r, c3r, ah0, ah1, ah2, ah3, bh0, bh1);
            mma_bf16(c0r, c1r, c2r, c3r, ah0, ah1, ah2, ah3, bl0, bl1);
            mma_bf16(c0r, c1r, c2r, c3r, al0, al1, al2, al3, bh0, bh1);
        }
    }
    __syncthreads();
    float* red = sm;
    if (wid < 16) {
        int ridx = kz * 544 + (mi * 16 + gid) * 17 + ni * 8 + tig * 2;
        red[ridx] = c0r; red[ridx + 1] = c1r;
        red[ridx + 136] = c2r; red[ridx + 137] = c3r;
    }
    __syncthreads();
    if (tid < 512) {
        int bl = tid & 31, chn = tid >> 5;
        float v = red[bl * 17 + chn] + red[544 + bl * 17 + chn]
                + red[1088 + bl * 17 + chn] + red[1632 + bl * 17 + chn];
        int c = c0 + chn, b = b0 + bl;
        if (mode) {
            v = tanh_fast(v + bias[c]);
            __nv_bfloat16 h = __float2bfloat16(v);
            g_t1p[0][c >> 1][b * 2 + (c & 1)] = h;
            g_t1p[1][c >> 1][b * 2 + (c & 1)] = __float2bfloat16(v - __bfloat162float(h));
        } else {
            g_dk[b][c] = v;
        }
    }
}

__global__ void __launch_bounds__(NTHR)
k_persist(const float* __restrict__ enc, const float* __restrict__ gt,
          const float* __restrict__ mask,
          const float* __restrict__ bi, const float* __restrict__ bh,
          const float* __restrict__ b1,
          const float* __restrict__ lw, const float* __restrict__ prior,
          float* __restrict__ out) {
    extern __shared__ __align__(16) float sm[];
    int bid = blockIdx.x, tid = threadIdx.x;
    int lane = tid & 31, wrp = tid >> 5;

    for (int t = 0;; t++) {
        int buf = t & 1, nbuf = buf ^ 1;
        unsigned gen = (unsigned)(t + 1);

        // ===== Phase A: wait pair F(t-1), softmax, prev, loc-conv + prior =====
        {
            int b = bid >> 1, half = bid & 1;
            float* s_al  = sm;
            float* s_mx  = sm + 256;
            float* s_sm2 = sm + 288;
            float* s_pt  = sm + 512;

            if (t > 0) {
                if (tid < 2) { while (ld_acq(&g_ff[(bid ^ tid) * 8]) < (unsigned)t) {} }
                __syncthreads();
            }

            float a = 0.f, e = 0.f;
            if (t == 0) {
                if (tid < 256) a = (tid == 0) ? 1.f : 0.f;
            } else if (tid < 256) {
                e = __ldcg(&g_energy[b][tid]);
                float m = e;
                #pragma unroll
                for (int o = 16; o; o >>= 1) m = fmaxf(m, __shfl_xor_sync(0xffffffffu, m, o));
                if (lane == 0) s_mx[wrp] = m;
            }
            __syncthreads();
            if (t > 0 && tid < 256) {
                float bm = s_mx[0];
                #pragma unroll
                for (int i = 1; i < 8; i++) bm = fmaxf(bm, s_mx[i]);
                float p = __expf(e - bm);
                float ws = p;
                #pragma unroll
                for (int o = 16; o; o >>= 1) ws += __shfl_xor_sync(0xffffffffu, ws, o);
                if (lane == 0) s_sm2[wrp] = ws;
                a = p;
            }
            __syncthreads();
            if (tid < 256) {
                if (t > 0) {
                    float tot = 0.f;
                    #pragma unroll
                    for (int i = 0; i < 8; i++) tot += s_sm2[i];
                    a = __fdividef(a, tot);
                    if (half == 0) out[((size_t)b * TT + (t - 1)) * SS + tid] = a;
                }
                s_al[tid] = a;
                if (half == 0) g_alpha[b][tid] = a;
            }
            __syncthreads();
            if (t == TT) break;

            if (half == 0 && tid < HH)
                st_pair(buf, tid, b, gt[((size_t)b * TT + t) * HH + tid]);

            {
                int si = tid >> 3, l = tid & 7;
                int sg = half * 128 + si;
                const float* wv = lw + l * 21;
                float acc = 0.f;
                #pragma unroll
                for (int k = 0; k < 21; k++) {
                    int ix = sg - 10 + k;
                    float av = (ix >= 0 && ix < 256) ? s_al[ix] : 0.f;
                    acc = fmaf(av, wv[k], acc);
                }
                g_lf[b][half][si][l] = acc;
                if (tid < 128) {
                    int sg2 = half * 128 + tid;
                    float pr = 0.f;
                    #pragma unroll
                    for (int k = 0; k < 11; k++) {
                        int ix = sg2 - 10 + k;
                        float av = (ix >= 0) ? s_al[ix] : 0.f;
                        pr = fmaf(av, prior[k], pr);
                    }
                    g_pri[b][half][tid] = pr;
                }
            }

            int col = tid & 255, slab = tid >> 8;
            const float* ep = enc + ((size_t)b * SS + slab * 64) * 512 + half * 256 + col;
            float acc0 = 0.f, acc1 = 0.f;
            #pragma unroll 8
            for (int s = 0; s < 64; s += 2) {
                acc0 = fmaf(s_al[slab * 64 + s], __ldcg(&ep[(size_t)s * 512]), acc0);
                acc1 = fmaf(s_al[slab * 64 + s + 1], __ldcg(&ep[(size_t)(s + 1) * 512]), acc1);
            }
            s_pt[tid] = acc0 + acc1;
            __syncthreads();
            if (tid < 256) {
                float v = s_pt[tid] + s_pt[256 + tid] + s_pt[512 + tid] + s_pt[768 + tid];
                st_pair(buf, HH + half * 256 + tid, b, v);
            }
        }
        __syncthreads();
        if (tid == 0) st_rel(&g_fa[bid * 8], gen);   // A done

        // ===== Phase B: q-first chunk order; A-wait hidden mid-loop ===========
        {
            int cg = bid >> 1, bt = bid & 1, b0 = bt * 32, c0 = cg * 32;
            char* smc = (char*)sm;
            const int RS = 160, TSZ = 32 * RS, BUF = 4 * TSZ;
            unsigned sbase = (unsigned)__cvta_generic_to_shared(smc);
            int row = (tid >> 3) & 31, seg = tid & 7, grp = tid >> 8;

            int wid2 = tid >> 5;
            int kz = wid2 & 3, tile = wid2 >> 2;
            int mi = tile & 1, ni = tile >> 1;
            int gid = lane >> 2, tig = lane & 3;
            int arow = (kz * 8 + tig) * RS;
            int aoff = arow + (mi * 16 + gid) * 4;
            int boff = arow + (ni * 8 + gid) * 4;
            float c0r = 0.f, c1r = 0.f, c2r = 0.f, c3r = 0.f;

            // logical ch -> phys chunk (ch+10)%18: q chunks (10-17) first, no A wait
            #pragma unroll
            for (int pg = 0; pg < 2; pg++) {
                int kc2 = (pg + 10) * 32;
                unsigned dst = sbase + (unsigned)(pg * BUF + grp * TSZ + row * RS + seg * 16);
                const char* src;
                if (grp == 0) src = (const char*)&g_xh[buf][kc2 + row][0] + b0 * 4 + seg * 16;
                else if (grp == 1) src = (const char*)&g_xl[buf][kc2 + row][0] + b0 * 4 + seg * 16;
                else if (grp == 2) src = (const char*)&g_wph[kc2 + row][0] + c0 * 4 + seg * 16;
                else src = (const char*)&g_wpl[kc2 + row][0] + c0 * 4 + seg * 16;
                if (grp < 2) cpg(dst, src); else cpw(dst, src);
                CPC;
            }
            for (int ch = 0; ch < 18; ch++) {
                if (ch < 17) CPW1; else CPW0;
                __syncthreads();
                if (ch == 6) {   // next prefetch (phys 0) needs frame+prev from A
                    if (tid < 64) { while (ld_acq(&g_fa[((bt << 6) + tid) * 8]) < gen) {} }
                    __syncthreads();
                }
                if (ch + 2 < 18) {
                    int kc2 = ((ch + 12) % 18) * 32, st = (ch + 2) % 3;
                    unsigned dst = sbase + (unsigned)(st * BUF + grp * TSZ + row * RS + seg * 16);
                    const char* src;
                    if (grp == 0) src = (const char*)&g_xh[buf][kc2 + row][0] + b0 * 4 + seg * 16;
                    else if (grp == 1) src = (const char*)&g_xl[buf][kc2 + row][0] + b0 * 4 + seg * 16;
                    else if (grp == 2) src = (const char*)&g_wph[kc2 + row][0] + c0 * 4 + seg * 16;
                    else src = (const char*)&g_wpl[kc2 + row][0] + c0 * 4 + seg * 16;
                    if (grp < 2) cpg(dst, src); else cpw(dst, src);
                    CPC;
                }
                const char* tb = smc + (ch % 3) * BUF;
                unsigned ah0 = *(const unsigned*)(tb + aoff);
                unsigned ah1 = *(const unsigned*)(tb + aoff + 32);
                unsigned ah2 = *(const unsigned*)(tb + aoff + 640);
                unsigned ah3 = *(const unsigned*)(tb + aoff + 672);
                unsigned al0 = *(const unsigned*)(tb + TSZ + aoff);
                unsigned al1 = *(const unsigned*)(tb + TSZ + aoff + 32);
                unsigned al2 = *(const unsigned*)(tb + TSZ + aoff + 640);
                unsigned al3 = *(const unsigned*)(tb + TSZ + aoff + 672);
                unsigned bh0 = *(const unsigned*)(tb + 2 * TSZ + boff);
                unsigned bh1 = *(const unsigned*)(tb + 2 * TSZ + boff + 640);
                unsigned bl0 = *(const unsigned*)(tb + 3 * TSZ + boff);
                unsigned bl1 = *(const unsigned*)(tb + 3 * TSZ + boff + 640);
                mma_bf16(c0r, c1r, c2r, c3r, ah0, ah1, ah2, ah3, bh0, bh1);
                mma_bf16(c0r, c1r, c2r, c3r, ah0, ah1, ah2, ah3, bl0, bl1);
                mma_bf16(c0r, c1r, c2r, c3r, al0, al1, al2, al3, bh0, bh1);
            }
            __syncthreads();
            float* red = sm;
            int ridx = kz * 1056 + (mi * 16 + gid) * 33 + ni * 8 + tig * 2;
            red[ridx] = c0r; red[ridx + 1] = c1r;
            red[ridx + 8 * 33] = c2r; red[ridx + 8 * 33 + 1] = c3r;
            __syncthreads();
            if (tid < 256) {
                int bl = tid & 31, chn = tid >> 5;
                float G[4];
                #pragma unroll
                for (int g = 0; g < 4; g++)
                    G[g] = red[bl * 33 + chn * 4 + g] + red[1056 + bl * 33 + chn * 4 + g]
                         + red[2112 + bl * 33 + chn * 4 + g] + red[3168 + bl * 33 + chn * 4 + g];
                int ch2 = cg * 8 + chn, bb2 = b0 + bl;
                float qold = __ldcg(&g_qf[ch2][bb2]);
                float rg = sig_fast(G[0] + bi[ch2] + bh[ch2]);
                float zg = sig_fast(G[1] + bi[512 + ch2] + bh[512 + ch2]);
                float ng = tanh_fast(G[2] + bi[1024 + ch2] + rg * (G[3] + bh[1024 + ch2]));
                float qn = (1.f - zg) * ng + zg * qold;
                g_qf[ch2][bb2] = qn;
                st_pair(nbuf, 592 + ch2, bb2, qn);
            }
        }
        __syncthreads();
        if (tid == 0) st_rel(&g_fb[bid * 8], gen);   // B done

        // ===== Phase D (blocks 0-63): wait B parity flags + E(t-1) flags ======
        if (bid < 64) {
            if (tid < 64) { while (ld_acq(&g_fb[((tid << 1) + (bid & 1)) * 8]) < gen) {} }
            else if (tid >= 64 && tid < 86) {
                while (ld_acq(&g_fe[(tid - 64) * 8]) < gen - 1u) {}
            }
            __syncthreads();
            mma16(&g_xh[nbuf][296][0], &g_xl[nbuf][296][0],
                  &g_w1p[0][0][0], &g_w1p[1][0][0], 1024,
                  (bid >> 1) * 16, (bid & 1) * 32, b1, 1, sm, tid);
            __syncthreads();
            if (tid == 0) st_rel(&g_df[bid * 8], gen);
            if (bid < 22) {
                if (tid < 64) { while (ld_acq(&g_df[tid * 8]) < gen) {} }
                __syncthreads();
                mma16(&g_t1p[0][0][0], &g_t1p[1][0][0],
                      &g_w2p[0][0][0], &g_w2p[1][0][0], 352,
                      (bid >> 1) * 16, (bid & 1) * 32, (const float*)0, 0, sm, tid);
                __syncthreads();
                if (tid == 0) st_rel(&g_fe[bid * 8], gen);
            }
        }

        // ===== Phase F: dyn conv + score (tanh.approx) + energy ===============
        {
            int b = bid >> 1, half = bid & 1, s0 = half * 128;
            int par = bid >> 6;
            float* s_a   = sm;
            float* s_dkk = sm + 160;
            float* s_ft  = sm + 512;
            float* s_pri = sm + 2560;
            float* s_sp  = sm + 2688;
            float* s_ps  = sm + 7808;

            #pragma unroll
            for (int it = 0; it < 5; it++)
                s_sp[tid + it * 1024] = ((const float*)g_sp)[tid + it * 1024];
            {
                int si = tid >> 3, l = tid & 7;
                s_ft[si * 16 + l] = g_lf[b][half][si][l];
            }
            if (tid < 128) s_pri[tid] = g_pri[b][half][tid];
            if (tid < 11) { while (ld_acq(&g_fe[((tid << 1) + par) * 8]) < gen) {} }
            else if (tid == 16) { while (ld_acq(&g_fa[(bid ^ 1) * 8]) < gen) {} }
            __syncthreads();

            if (tid < 148) {
                int s = s0 - 10 + tid;
                s_a[tid] = (s >= 0 && s < SS) ? __ldcg(&g_alpha[b][s]) : 0.f;
            }
            if (tid >= 328 && tid < 496) s_dkk[tid - 328] = __ldcg(&g_dk[b][tid - 328]);
            __syncthreads();

            {
                int si = tid >> 3, l = tid & 7;
                const float* wv = &s_dkk[l * 21];
                float a = 0.f;
                #pragma unroll
                for (int k = 0; k < 21; k++) a = fmaf(s_a[si + k], wv[k], a);
                s_ft[si * 16 + 8 + l] = a;
            }
            __syncthreads();

            int si = tid & 127, sl = tid >> 7;
            const ulonglong2* fp = (const ulonglong2*)&s_ft[si * 16];
            ulonglong2 f01 = fp[0], f23 = fp[1], f45 = fp[2], f67 = fp[3];
            float part = 0.f;
            for (int c = sl * 32; c < sl * 32 + 32; c++) {
                const float* P = &s_sp[c * 20];
                const ulonglong2* pp = (const ulonglong2*)P;
                ulonglong2 p01 = pp[0], p23 = pp[1], p45 = pp[2], p67 = pp[3];
                unsigned long long acc = (unsigned long long)__float_as_uint(P[16]);
                fma2(acc, p01.x, f01.x); fma2(acc, p01.y, f01.y);
                fma2(acc, p23.x, f23.x); fma2(acc, p23.y, f23.y);
                fma2(acc, p45.x, f45.x); fma2(acc, p45.y, f45.y);
                fma2(acc, p67.x, f67.x); fma2(acc, p67.y, f67.y);
                float sc = __uint_as_float((unsigned)acc) +
                           __uint_as_float((unsigned)(acc >> 32));
                part = fmaf(P[17], tanh_mufu(sc), part);
            }
            s_ps[sl * 128 + si] = part;
            __syncthreads();
            if (tid < 128) {
                float e = 0.f;
                #pragma unroll
                for (int i = 0; i < 8; i++) e += s_ps[i * 128 + tid];
                e += __logf(s_pri[tid] + 1e-5f);
                int s = s0 + tid;
                e = (mask[b * SS + s] > 0.f) ? e : -INFINITY;
                g_energy[b][s] = e;
            }
        }
        __syncthreads();
        if (tid == 0) st_rel(&g_ff[bid * 8], gen);   // F done
    }
}

extern "C" void kernel_launch(void* const* d_in, const int* in_sizes, int n_in,
                              void* d_out, int out_size) {
    const float* enc   = (const float*)d_in[0];
    const float* mask  = (const float*)d_in[1];
    const float* gt    = (const float*)d_in[2];
    const float* wi    = (const float*)d_in[3];
    const float* wh    = (const float*)d_in[4];
    const float* bi    = (const float*)d_in[5];
    const float* bh    = (const float*)d_in[6];
    const float* lw    = (const float*)d_in[7];
    const float* lp    = (const float*)d_in[8];
    const float* w1    = (const float*)d_in[9];
    const float* b1    = (const float*)d_in[10];
    const float* w2    = (const float*)d_in[11];
    const float* dw    = (const float*)d_in[12];
    const float* db    = (const float*)d_in[13];
    const float* aw    = (const float*)d_in[14];
    const float* prior = (const float*)d_in[15];
    float* out = (float*)d_out;

    static int cfg_done = 0;
    if (!cfg_done) {
        cudaFuncSetAttribute(k_persist, cudaFuncAttributeMaxDynamicSharedMemorySize, 65536);
        cfg_done = 1;
    }
    k_init<<<512, 256>>>(wi, wh, w1, w2, lp, dw, db, aw);
    k_persist<<<GRID, NTHR, 65536>>>(enc, gt, mask, bi, bh, b1, lw, prior, out);
}